// round 1
// baseline (speedup 1.0000x reference)
#include <cuda_runtime.h>
#include <math.h>

#define NROI 4096
#define DIM  1024
#define HID  512
#define NCLS 21
#define NBBX 84          // 4*21
#define NW   128         // adjacency words per row (4096/32)
#define KSPLIT 8

// ---------------- scratch (static device globals; no allocation) -------------
__device__ float    g_xn[NROI * DIM];
__device__ float    g_d[NROI];
__device__ float    g_t1[NROI * HID];
__device__ float    g_u1[DIM * HID];
__device__ float    g_u2[DIM * HID];
__device__ float    g_upart[KSPLIT * DIM * HID];
__device__ float    g_h1[NROI * HID];
__device__ float    g_t2[NROI * HID];
__device__ float    g_h2[NROI * HID];
__device__ unsigned g_adj[NROI * NW];
__device__ int      g_lab[2][NROI];
__device__ float    g_logits[NROI * NCLS];

// ---------------- adjacency bitmask: bit set iff IoU > 0 (i != j) ------------
// iou > 0  <=>  inter > 0  <=>  iw > 0 && ih > 0
__global__ void adj_kernel(const float* __restrict__ rois) {
    int idx = blockIdx.x * blockDim.x + threadIdx.x;
    int i = idx >> 7;          // row
    int w = idx & (NW - 1);    // word
    if (i >= NROI) return;
    float x1 = rois[i * 4 + 0], y1 = rois[i * 4 + 1];
    float x2 = rois[i * 4 + 2], y2 = rois[i * 4 + 3];
    unsigned bits = 0;
    int jb = w * 32;
#pragma unroll 4
    for (int k = 0; k < 32; k++) {
        int j = jb + k;
        float bx1 = rois[j * 4 + 0], by1 = rois[j * 4 + 1];
        float bx2 = rois[j * 4 + 2], by2 = rois[j * 4 + 3];
        float iw = fminf(x2, bx2) - fmaxf(x1, bx1) + 1.0f;
        float ih = fminf(y2, by2) - fmaxf(y1, by1) + 1.0f;
        if (iw > 0.0f && ih > 0.0f && j != i) bits |= (1u << k);
    }
    g_adj[i * NW + w] = bits;
}

__global__ void init_labels_kernel() {
    int i = blockIdx.x * blockDim.x + threadIdx.x;
    if (i < NROI) g_lab[0][i] = i;
}

// One reference iteration = J (pointer jump) then P (min propagate), fused as
// l_new = P(J(l_prev)); a final standalone J is applied in labels_out_kernel.
__global__ void prop_kernel(int src) {
    __shared__ int sl[NROI];
    __shared__ int slj[NROI];
    __shared__ int wmin[NW];
    const int* lp = g_lab[src];
    int* lo = g_lab[src ^ 1];
    int tid = threadIdx.x;
    for (int k = tid; k < NROI; k += 256) sl[k] = lp[k];
    __syncthreads();
    for (int k = tid; k < NROI; k += 256) slj[k] = sl[sl[k]];
    __syncthreads();
    if (tid < NW) {
        int m = NROI;
#pragma unroll 8
        for (int b = 0; b < 32; b++) m = min(m, slj[tid * 32 + b]);
        wmin[tid] = m;
    }
    __syncthreads();
    int i = blockIdx.x * 256 + tid;
    int nb = slj[i];                        // implements labels = min(labels, nb)
    const unsigned* arow = &g_adj[i * NW];
    for (int j = 0; j < NW; j++) {
        unsigned wb = arow[j];
        if (wb == 0xFFFFFFFFu) {
            nb = min(nb, wmin[j]);          // full word: use precomputed min
        } else {
            while (wb) {
                int b = __ffs(wb) - 1;
                wb &= wb - 1;
                nb = min(nb, slj[j * 32 + b]);
            }
        }
    }
    lo[i] = nb;
}

__global__ void labels_out_kernel(float* __restrict__ out) {
    int i = blockIdx.x * blockDim.x + threadIdx.x;
    if (i < NROI) {
        int v = g_lab[0][i];
        out[i] = (float)g_lab[0][v];        // final pointer jump + cast
    }
}

// ---------------- row-normalize pooled_feat; d_i = xn_i . xn_i ---------------
__global__ void normalize_kernel(const float* __restrict__ pf) {
    __shared__ float red[256];
    int row = blockIdx.x;
    const float* x = pf + (size_t)row * DIM;
    float ss = 0.f;
    for (int k = threadIdx.x; k < DIM; k += 256) { float v = x[k]; ss += v * v; }
    red[threadIdx.x] = ss;
    __syncthreads();
    for (int s = 128; s > 0; s >>= 1) {
        if (threadIdx.x < s) red[threadIdx.x] += red[threadIdx.x + s];
        __syncthreads();
    }
    float tot = red[0];
    float sc = 1.0f / fmaxf(sqrtf(tot), 1e-6f);
    for (int k = threadIdx.x; k < DIM; k += 256) g_xn[(size_t)row * DIM + k] = x[k] * sc;
    if (threadIdx.x == 0) g_d[row] = (tot * sc) * sc;
}

// ---------------- generic fp32 tiled GEMM ------------------------------------
// C[M,N] = A @ B  (A: (m,k)=A[m*lda+k], or (m,k)=A[k*lda+m] if TA)
// EPI 0: store   EPI 1: relu(acc - d[m]*T[m*ldc+n] + bias[n])   EPI 2: acc+bias
#define BM 64
#define BN 64
#define BK 16
#define SPAD 68

template<bool TA, int EPI>
__global__ void __launch_bounds__(256) gemm_kernel(
    const float* __restrict__ A, const float* __restrict__ B, float* __restrict__ C,
    int M, int N, int K, int lda, int ldb, int ldc, int kChunk,
    const float* __restrict__ bias, const float* __restrict__ dvec,
    const float* __restrict__ Tm)
{
    __shared__ __align__(16) float As[BK][SPAD];
    __shared__ __align__(16) float Bs[BK][SPAD];
    int m0 = blockIdx.y * BM;
    int n0 = blockIdx.x * BN;
    int k0 = blockIdx.z * kChunk;
    int kEnd = min(K, k0 + kChunk);
    if (gridDim.z > 1) C += (size_t)blockIdx.z * M * ldc;  // split-K partials
    int tid = threadIdx.x;
    int tx = tid & 15, ty = tid >> 4;
    float acc[4][4] = {};

    for (int kt = k0; kt < kEnd; kt += BK) {
        if (!TA) {
            int kk = tid & 15, mm = tid >> 4;
#pragma unroll
            for (int p = 0; p < 4; p++) {
                int m = mm + p * 16;
                int gm = m0 + m;
                float v = 0.f;
                if (gm < M) v = A[(size_t)gm * lda + (kt + kk)];
                As[kk][m] = v;
            }
        } else {
            int mm = tid & 63, kk = tid >> 6;
#pragma unroll
            for (int p = 0; p < 4; p++) {
                int k = kk + p * 4;
                int gm = m0 + mm;
                float v = 0.f;
                if (gm < M) v = A[(size_t)(kt + k) * lda + gm];
                As[k][mm] = v;
            }
        }
        {
            int nn = tid & 63, kk = tid >> 6;
#pragma unroll
            for (int p = 0; p < 4; p++) {
                int k = kk + p * 4;
                int gn = n0 + nn;
                float v = 0.f;
                if (gn < N) v = B[(size_t)(kt + k) * ldb + gn];
                Bs[k][nn] = v;
            }
        }
        __syncthreads();
#pragma unroll
        for (int kk = 0; kk < BK; kk++) {
            float4 a4 = *reinterpret_cast<const float4*>(&As[kk][ty * 4]);
            float4 b4 = *reinterpret_cast<const float4*>(&Bs[kk][tx * 4]);
            float a[4] = {a4.x, a4.y, a4.z, a4.w};
            float b[4] = {b4.x, b4.y, b4.z, b4.w};
#pragma unroll
            for (int i = 0; i < 4; i++)
#pragma unroll
                for (int j = 0; j < 4; j++)
                    acc[i][j] = fmaf(a[i], b[j], acc[i][j]);
        }
        __syncthreads();
    }

#pragma unroll
    for (int i = 0; i < 4; i++) {
        int gm = m0 + ty * 4 + i;
        if (gm >= M) continue;
        float dv = (EPI == 1) ? dvec[gm] : 0.f;
#pragma unroll
        for (int j = 0; j < 4; j++) {
            int gn = n0 + tx * 4 + j;
            if (gn >= N) continue;
            float v = acc[i][j];
            if (EPI == 1) {
                v = v - dv * Tm[(size_t)gm * ldc + gn] + bias[gn];
                v = fmaxf(v, 0.f);
            } else if (EPI == 2) {
                v += bias[gn];
            }
            C[(size_t)gm * ldc + gn] = v;
        }
    }
}

__global__ void reduceK_kernel(const float* __restrict__ part, float* __restrict__ outb,
                               int total, int parts) {
    int i = blockIdx.x * blockDim.x + threadIdx.x;
    if (i >= total) return;
    float s = 0.f;
    for (int p = 0; p < parts; p++) s += part[(size_t)p * total + i];
    outb[i] = s;
}

// ---------------- softmax over 21 classes, one warp per row ------------------
__global__ void softmax_kernel(float* __restrict__ out) {
    int row = blockIdx.x * 8 + (threadIdx.x >> 5);
    int lane = threadIdx.x & 31;
    if (row >= NROI) return;
    float v = (lane < NCLS) ? g_logits[row * NCLS + lane] : -INFINITY;
    float m = v;
#pragma unroll
    for (int o = 16; o; o >>= 1) m = fmaxf(m, __shfl_xor_sync(0xffffffffu, m, o));
    float e = (lane < NCLS) ? expf(v - m) : 0.f;
    float s = e;
#pragma unroll
    for (int o = 16; o; o >>= 1) s += __shfl_xor_sync(0xffffffffu, s, o);
    if (lane < NCLS) out[NROI + row * NCLS + lane] = e / s;
}

// -----------------------------------------------------------------------------
extern "C" void kernel_launch(void* const* d_in, const int* in_sizes, int n_in,
                              void* d_out, int out_size) {
    const float* rois   = (const float*)d_in[0];
    const float* pf     = (const float*)d_in[1];
    const float* Wg1    = (const float*)d_in[2];
    const float* bg1    = (const float*)d_in[3];
    const float* Wg2    = (const float*)d_in[4];
    const float* bg2    = (const float*)d_in[5];
    const float* W_bbox = (const float*)d_in[6];
    const float* b_bbox = (const float*)d_in[7];
    const float* W_cls  = (const float*)d_in[8];
    const float* b_cls  = (const float*)d_in[9];
    float* out = (float*)d_out;

    float *xn, *dv, *t1, *u1, *u2, *upart, *h1, *t2, *h2, *logits;
    cudaGetSymbolAddress((void**)&xn,     g_xn);
    cudaGetSymbolAddress((void**)&dv,     g_d);
    cudaGetSymbolAddress((void**)&t1,     g_t1);
    cudaGetSymbolAddress((void**)&u1,     g_u1);
    cudaGetSymbolAddress((void**)&u2,     g_u2);
    cudaGetSymbolAddress((void**)&upart,  g_upart);
    cudaGetSymbolAddress((void**)&h1,     g_h1);
    cudaGetSymbolAddress((void**)&t2,     g_t2);
    cudaGetSymbolAddress((void**)&h2,     g_h2);
    cudaGetSymbolAddress((void**)&logits, g_logits);

    // ---- connected components front half ----
    init_labels_kernel<<<16, 256>>>();
    adj_kernel<<<(NROI * NW) / 256, 256>>>(rois);

    // ---- normalize ----
    normalize_kernel<<<NROI, 256>>>(pf);

    const int utotal = DIM * HID;

    // t1 = pooled @ Wg1     [4096,512] K=1024
    gemm_kernel<false, 0><<<dim3(HID / BN, NROI / BM, 1), 256>>>(
        pf, Wg1, t1, NROI, HID, DIM, DIM, HID, HID, DIM, nullptr, nullptr, nullptr);

    // u1 = xn^T @ t1        [1024,512] K=4096, split-K
    gemm_kernel<true, 0><<<dim3(HID / BN, DIM / BM, KSPLIT), 256>>>(
        xn, t1, upart, DIM, HID, NROI, DIM, HID, HID, NROI / KSPLIT,
        nullptr, nullptr, nullptr);
    reduceK_kernel<<<(utotal + 255) / 256, 256>>>(upart, u1, utotal, KSPLIT);

    // h1 = relu(xn @ u1 - d*t1 + bg1)
    gemm_kernel<false, 1><<<dim3(HID / BN, NROI / BM, 1), 256>>>(
        xn, u1, h1, NROI, HID, DIM, DIM, HID, HID, DIM, bg1, dv, t1);

    // t2 = h1 @ Wg2         [4096,512] K=512
    gemm_kernel<false, 0><<<dim3(HID / BN, NROI / BM, 1), 256>>>(
        h1, Wg2, t2, NROI, HID, HID, HID, HID, HID, HID, nullptr, nullptr, nullptr);

    // u2 = xn^T @ t2
    gemm_kernel<true, 0><<<dim3(HID / BN, DIM / BM, KSPLIT), 256>>>(
        xn, t2, upart, DIM, HID, NROI, DIM, HID, HID, NROI / KSPLIT,
        nullptr, nullptr, nullptr);
    reduceK_kernel<<<(utotal + 255) / 256, 256>>>(upart, u2, utotal, KSPLIT);

    // h2 = relu(xn @ u2 - d*t2 + bg2)
    gemm_kernel<false, 1><<<dim3(HID / BN, NROI / BM, 1), 256>>>(
        xn, u2, h2, NROI, HID, DIM, DIM, HID, HID, DIM, bg2, dv, t2);

    // bbox_pred = h2 @ W_bbox + b_bbox -> out[NROI + NROI*NCLS ...]
    gemm_kernel<false, 2><<<dim3((NBBX + BN - 1) / BN, NROI / BM, 1), 256>>>(
        h2, W_bbox, out + NROI + (size_t)NROI * NCLS,
        NROI, NBBX, HID, HID, NBBX, NBBX, HID, b_bbox, nullptr, nullptr);

    // cls logits = h2 @ W_cls + b_cls, then softmax -> out[NROI ...]
    gemm_kernel<false, 2><<<dim3(1, NROI / BM, 1), 256>>>(
        h2, W_cls, logits, NROI, NCLS, HID, HID, NCLS, NCLS, HID,
        b_cls, nullptr, nullptr);
    softmax_kernel<<<NROI / 8, 256>>>(out);

    // ---- 32 label-propagation iterations (fused jump+propagate) ----
    for (int it = 0; it < 32; it++) prop_kernel<<<NROI / 256, 256>>>(it & 1);
    labels_out_kernel<<<16, 256>>>(out);
}

// round 2
// speedup vs baseline: 4.4571x; 4.4571x over previous
#include <cuda_runtime.h>
#include <math.h>

#define NROI 4096
#define DIM  1024
#define HID  512
#define NCLS 21
#define NBBX 84          // 4*21
#define NW   128         // adjacency words per row (4096/32)
#define KSPLIT 8

// ---------------- scratch (static device globals; no allocation) -------------
__device__ float    g_xn[NROI * DIM];
__device__ float    g_d[NROI];
__device__ float    g_t1[NROI * HID];
__device__ float    g_u1[DIM * HID];
__device__ float    g_u2[DIM * HID];
__device__ float    g_upart[KSPLIT * DIM * HID];
__device__ float    g_h1[NROI * HID];
__device__ float    g_t2[NROI * HID];
__device__ float    g_h2[NROI * HID];
__device__ unsigned g_adj[NROI * NW];
__device__ int      g_lab[2][NROI];
__device__ float    g_logits[NROI * NCLS];
__device__ int      g_conv;
__device__ int      g_diff;

// ---------------- adjacency bitmask: bit set iff IoU > 0 (i != j) ------------
__global__ void adj_kernel(const float* __restrict__ rois) {
    int idx = blockIdx.x * blockDim.x + threadIdx.x;
    int i = idx >> 7;          // row
    int w = idx & (NW - 1);    // word
    if (i >= NROI) return;
    float4 bi = *reinterpret_cast<const float4*>(&rois[i * 4]);
    unsigned bits = 0;
    int jb = w * 32;
#pragma unroll 4
    for (int k = 0; k < 32; k++) {
        int j = jb + k;
        float4 bj = *reinterpret_cast<const float4*>(&rois[j * 4]);
        float iw = fminf(bi.z, bj.z) - fmaxf(bi.x, bj.x) + 1.0f;
        float ih = fminf(bi.w, bj.w) - fmaxf(bi.y, bj.y) + 1.0f;
        if (iw > 0.0f && ih > 0.0f && j != i) bits |= (1u << k);
    }
    g_adj[i * NW + w] = bits;
}

__global__ void init_labels_kernel() {
    int i = blockIdx.x * blockDim.x + threadIdx.x;
    if (i < NROI) g_lab[0][i] = i;
    if (i == 0) { g_conv = 0; g_diff = 0; }
}

// One reference iteration = P(J(l)); final standalone J applied at output.
// Early-exits (bit-exactly) once labels reach the fixpoint.
__global__ void __launch_bounds__(256) prop_kernel(int src) {
    if (*(volatile int*)&g_conv) return;
    __shared__ int slj[NROI];
    __shared__ int wmin[NW];
    const int* __restrict__ lp = g_lab[src];
    int* __restrict__ lo = g_lab[src ^ 1];
    int tid = threadIdx.x;
    for (int k = tid; k < NROI; k += 256) slj[k] = lp[lp[k]];
    __syncthreads();
    if (tid < NW) {
        int m = slj[tid * 32];
#pragma unroll
        for (int b = 1; b < 32; b++) m = min(m, slj[tid * 32 + b]);
        wmin[tid] = m;
    }
    __syncthreads();
    int warp = tid >> 5, lane = tid & 31;
    int rbase = blockIdx.x * 32 + warp * 4;
#pragma unroll
    for (int r = 0; r < 4; r++) {
        int i = rbase + r;
        const unsigned* __restrict__ arow = &g_adj[(size_t)i * NW];
        int nb = slj[i];
#pragma unroll
        for (int q = 0; q < 4; q++) {
            int w = lane + q * 32;
            unsigned wb = arow[w];
            if (wb == 0xFFFFFFFFu) {
                nb = min(nb, wmin[w]);
            } else {
                while (wb) {
                    int b = __ffs(wb) - 1;
                    wb &= wb - 1;
                    nb = min(nb, slj[w * 32 + b]);
                }
            }
        }
#pragma unroll
        for (int o = 16; o; o >>= 1) nb = min(nb, __shfl_xor_sync(0xffffffffu, nb, o));
        if (lane == 0) {
            lo[i] = nb;
            if (nb != lp[i]) g_diff = 1;
        }
    }
}

__global__ void conv_finalize_kernel() {
    if (g_conv == 0 && g_diff == 0) g_conv = 1;
    g_diff = 0;
}

__global__ void labels_out_kernel(float* __restrict__ out) {
    int i = blockIdx.x * blockDim.x + threadIdx.x;
    if (i < NROI) {
        int v = g_lab[0][i];
        out[i] = (float)g_lab[0][v];        // final pointer jump + cast
    }
}

// ---------------- row-normalize pooled_feat; d_i = xn_i . xn_i ---------------
__global__ void normalize_kernel(const float* __restrict__ pf) {
    __shared__ float red[256];
    int row = blockIdx.x;
    const float4* x = reinterpret_cast<const float4*>(pf + (size_t)row * DIM);
    float4 v = x[threadIdx.x];
    float ss = v.x * v.x + v.y * v.y + v.z * v.z + v.w * v.w;
    red[threadIdx.x] = ss;
    __syncthreads();
    for (int s = 128; s > 0; s >>= 1) {
        if (threadIdx.x < s) red[threadIdx.x] += red[threadIdx.x + s];
        __syncthreads();
    }
    float tot = red[0];
    float sc = 1.0f / fmaxf(sqrtf(tot), 1e-6f);
    float4 o = make_float4(v.x * sc, v.y * sc, v.z * sc, v.w * sc);
    reinterpret_cast<float4*>(g_xn + (size_t)row * DIM)[threadIdx.x] = o;
    if (threadIdx.x == 0) g_d[row] = (tot * sc) * sc;
}

// ---------------- f32x2 packed-FMA tiled GEMM --------------------------------
// C[M,N] = A @ B   (A[m*lda+k], or A[k*lda+m] if TA). M%128==0, N%64==0, K%16==0.
// EPI 0: store   EPI 1: relu(acc - d[m]*T[m*ldc+n] + bias[n])
__device__ __forceinline__ void fma2(unsigned long long& d, unsigned long long a,
                                     unsigned long long b) {
    asm("fma.rn.f32x2 %0, %1, %2, %0;" : "+l"(d) : "l"(a), "l"(b));
}
__device__ __forceinline__ unsigned long long dup2(float b) {
    unsigned long long r;
    asm("mov.b64 %0, {%1, %1};" : "=l"(r) : "f"(b));
    return r;
}
__device__ __forceinline__ float2 unpk(unsigned long long v) {
    unsigned lo = (unsigned)v, hi = (unsigned)(v >> 32);
    return make_float2(__uint_as_float(lo), __uint_as_float(hi));
}

#define GBM 128
#define GBN 64
#define GBK 16
#define APAD 132
#define BPAD 68

template<bool TA, int EPI>
__global__ void __launch_bounds__(256) gemm2_kernel(
    const float* __restrict__ A, const float* __restrict__ B, float* __restrict__ C,
    int M, int N, int K, int lda, int ldb, int ldc, int kChunk,
    const float* __restrict__ bias, const float* __restrict__ dvec,
    const float* __restrict__ Tm)
{
    __shared__ __align__(16) float As[GBK][APAD];
    __shared__ __align__(16) float Bs[GBK][BPAD];
    int m0 = blockIdx.y * GBM;
    int n0 = blockIdx.x * GBN;
    int k0 = blockIdx.z * kChunk;
    int kEnd = min(K, k0 + kChunk);
    if (gridDim.z > 1) C += (size_t)blockIdx.z * M * ldc;
    int tid = threadIdx.x;
    int tx = tid & 15, ty = tid >> 4;        // tx: n (4 each), ty: m (8 each)

    unsigned long long acc[4][4];            // [m-pair][n]
#pragma unroll
    for (int i = 0; i < 4; i++)
#pragma unroll
        for (int j = 0; j < 4; j++) acc[i][j] = 0ULL;

    for (int kt = k0; kt < kEnd; kt += GBK) {
        if (!TA) {
            int row = tid >> 1;
            int kq = (tid & 1) * 4;
#pragma unroll
            for (int it = 0; it < 2; it++) {
                int kk = kq + it * 8;
                float4 v = *reinterpret_cast<const float4*>(
                    &A[(size_t)(m0 + row) * lda + kt + kk]);
                As[kk + 0][row] = v.x;
                As[kk + 1][row] = v.y;
                As[kk + 2][row] = v.z;
                As[kk + 3][row] = v.w;
            }
        } else {
            int kk = tid >> 4, mseg = tid & 15;
#pragma unroll
            for (int it = 0; it < 2; it++) {
                float4 v = *reinterpret_cast<const float4*>(
                    &A[(size_t)(kt + kk) * lda + m0 + mseg * 8 + it * 4]);
                *reinterpret_cast<float4*>(&As[kk][mseg * 8 + it * 4]) = v;
            }
        }
        {
            int kb = tid >> 4, nq = tid & 15;
            float4 v = *reinterpret_cast<const float4*>(
                &B[(size_t)(kt + kb) * ldb + n0 + nq * 4]);
            *reinterpret_cast<float4*>(&Bs[kb][nq * 4]) = v;
        }
        __syncthreads();
#pragma unroll
        for (int kk = 0; kk < GBK; kk++) {
            const unsigned long long* ap =
                reinterpret_cast<const unsigned long long*>(&As[kk][ty * 8]);
            unsigned long long a0 = ap[0], a1 = ap[1], a2 = ap[2], a3 = ap[3];
            float4 b4 = *reinterpret_cast<const float4*>(&Bs[kk][tx * 4]);
            unsigned long long bd0 = dup2(b4.x), bd1 = dup2(b4.y);
            unsigned long long bd2 = dup2(b4.z), bd3 = dup2(b4.w);
            fma2(acc[0][0], a0, bd0); fma2(acc[0][1], a0, bd1);
            fma2(acc[0][2], a0, bd2); fma2(acc[0][3], a0, bd3);
            fma2(acc[1][0], a1, bd0); fma2(acc[1][1], a1, bd1);
            fma2(acc[1][2], a1, bd2); fma2(acc[1][3], a1, bd3);
            fma2(acc[2][0], a2, bd0); fma2(acc[2][1], a2, bd1);
            fma2(acc[2][2], a2, bd2); fma2(acc[2][3], a2, bd3);
            fma2(acc[3][0], a3, bd0); fma2(acc[3][1], a3, bd1);
            fma2(acc[3][2], a3, bd2); fma2(acc[3][3], a3, bd3);
        }
        __syncthreads();
    }

    float4 bias4;
    if (EPI == 1) bias4 = *reinterpret_cast<const float4*>(&bias[n0 + tx * 4]);
#pragma unroll
    for (int ip = 0; ip < 4; ip++) {
#pragma unroll
        for (int half = 0; half < 2; half++) {
            int gm = m0 + ty * 8 + ip * 2 + half;
            float r0 = half ? unpk(acc[ip][0]).y : unpk(acc[ip][0]).x;
            float r1 = half ? unpk(acc[ip][1]).y : unpk(acc[ip][1]).x;
            float r2 = half ? unpk(acc[ip][2]).y : unpk(acc[ip][2]).x;
            float r3 = half ? unpk(acc[ip][3]).y : unpk(acc[ip][3]).x;
            float4 res;
            if (EPI == 1) {
                float dv = dvec[gm];
                float4 tm = *reinterpret_cast<const float4*>(
                    &Tm[(size_t)gm * ldc + n0 + tx * 4]);
                res.x = fmaxf(r0 - dv * tm.x + bias4.x, 0.f);
                res.y = fmaxf(r1 - dv * tm.y + bias4.y, 0.f);
                res.z = fmaxf(r2 - dv * tm.z + bias4.z, 0.f);
                res.w = fmaxf(r3 - dv * tm.w + bias4.w, 0.f);
            } else {
                res = make_float4(r0, r1, r2, r3);
            }
            *reinterpret_cast<float4*>(&C[(size_t)gm * ldc + n0 + tx * 4]) = res;
        }
    }
}

// ---------------- small fallback GEMM (guarded, for N=84 / N=21 heads) -------
#define BM 64
#define BN 64
#define BK 16
#define SPAD 68
__global__ void __launch_bounds__(256) gemm_small_kernel(
    const float* __restrict__ A, const float* __restrict__ B, float* __restrict__ C,
    int M, int N, int K, int lda, int ldb, int ldc,
    const float* __restrict__ bias)
{
    __shared__ __align__(16) float As[BK][SPAD];
    __shared__ __align__(16) float Bs[BK][SPAD];
    int m0 = blockIdx.y * BM;
    int n0 = blockIdx.x * BN;
    int tid = threadIdx.x;
    int tx = tid & 15, ty = tid >> 4;
    float acc[4][4] = {};
    for (int kt = 0; kt < K; kt += BK) {
        {
            int kk = tid & 15, mm = tid >> 4;
#pragma unroll
            for (int p = 0; p < 4; p++) {
                int m = mm + p * 16;
                As[kk][m] = A[(size_t)(m0 + m) * lda + (kt + kk)];
            }
        }
        {
            int nn = tid & 63, kk = tid >> 6;
#pragma unroll
            for (int p = 0; p < 4; p++) {
                int k = kk + p * 4;
                int gn = n0 + nn;
                Bs[k][nn] = (gn < N) ? B[(size_t)(kt + k) * ldb + gn] : 0.f;
            }
        }
        __syncthreads();
#pragma unroll
        for (int kk = 0; kk < BK; kk++) {
            float4 a4 = *reinterpret_cast<const float4*>(&As[kk][ty * 4]);
            float4 b4 = *reinterpret_cast<const float4*>(&Bs[kk][tx * 4]);
            float a[4] = {a4.x, a4.y, a4.z, a4.w};
            float b[4] = {b4.x, b4.y, b4.z, b4.w};
#pragma unroll
            for (int i = 0; i < 4; i++)
#pragma unroll
                for (int j = 0; j < 4; j++)
                    acc[i][j] = fmaf(a[i], b[j], acc[i][j]);
        }
        __syncthreads();
    }
#pragma unroll
    for (int i = 0; i < 4; i++) {
        int gm = m0 + ty * 4 + i;
#pragma unroll
        for (int j = 0; j < 4; j++) {
            int gn = n0 + tx * 4 + j;
            if (gn < N) C[(size_t)gm * ldc + gn] = acc[i][j] + bias[gn];
        }
    }
}

__global__ void reduceK_kernel(const float* __restrict__ part, float* __restrict__ outb,
                               int total, int parts) {
    int i = blockIdx.x * blockDim.x + threadIdx.x;
    if (i >= total) return;
    float s = 0.f;
    for (int p = 0; p < parts; p++) s += part[(size_t)p * total + i];
    outb[i] = s;
}

// ---------------- softmax over 21 classes, one warp per row ------------------
__global__ void softmax_kernel(float* __restrict__ out) {
    int row = blockIdx.x * 8 + (threadIdx.x >> 5);
    int lane = threadIdx.x & 31;
    if (row >= NROI) return;
    float v = (lane < NCLS) ? g_logits[row * NCLS + lane] : -INFINITY;
    float m = v;
#pragma unroll
    for (int o = 16; o; o >>= 1) m = fmaxf(m, __shfl_xor_sync(0xffffffffu, m, o));
    float e = (lane < NCLS) ? expf(v - m) : 0.f;
    float s = e;
#pragma unroll
    for (int o = 16; o; o >>= 1) s += __shfl_xor_sync(0xffffffffu, s, o);
    if (lane < NCLS) out[NROI + row * NCLS + lane] = e / s;
}

// -----------------------------------------------------------------------------
extern "C" void kernel_launch(void* const* d_in, const int* in_sizes, int n_in,
                              void* d_out, int out_size) {
    const float* rois   = (const float*)d_in[0];
    const float* pf     = (const float*)d_in[1];
    const float* Wg1    = (const float*)d_in[2];
    const float* bg1    = (const float*)d_in[3];
    const float* Wg2    = (const float*)d_in[4];
    const float* bg2    = (const float*)d_in[5];
    const float* W_bbox = (const float*)d_in[6];
    const float* b_bbox = (const float*)d_in[7];
    const float* W_cls  = (const float*)d_in[8];
    const float* b_cls  = (const float*)d_in[9];
    float* out = (float*)d_out;

    float *xn, *dv, *t1, *u1, *u2, *upart, *h1, *t2, *h2, *logits;
    cudaGetSymbolAddress((void**)&xn,     g_xn);
    cudaGetSymbolAddress((void**)&dv,     g_d);
    cudaGetSymbolAddress((void**)&t1,     g_t1);
    cudaGetSymbolAddress((void**)&u1,     g_u1);
    cudaGetSymbolAddress((void**)&u2,     g_u2);
    cudaGetSymbolAddress((void**)&upart,  g_upart);
    cudaGetSymbolAddress((void**)&h1,     g_h1);
    cudaGetSymbolAddress((void**)&t2,     g_t2);
    cudaGetSymbolAddress((void**)&h2,     g_h2);
    cudaGetSymbolAddress((void**)&logits, g_logits);

    // ---- connected components ----
    init_labels_kernel<<<16, 256>>>();
    adj_kernel<<<(NROI * NW) / 256, 256>>>(rois);
    for (int it = 0; it < 32; it++) {
        prop_kernel<<<NROI / 32, 256>>>(it & 1);
        conv_finalize_kernel<<<1, 1>>>();
    }
    labels_out_kernel<<<16, 256>>>(out);

    // ---- normalize ----
    normalize_kernel<<<NROI, 256>>>(pf);

    const int utotal = DIM * HID;

    // t1 = pooled @ Wg1     [4096,512] K=1024
    gemm2_kernel<false, 0><<<dim3(HID / GBN, NROI / GBM, 1), 256>>>(
        pf, Wg1, t1, NROI, HID, DIM, DIM, HID, HID, DIM, nullptr, nullptr, nullptr);

    // u1 = xn^T @ t1        [1024,512] K=4096, split-K
    gemm2_kernel<true, 0><<<dim3(HID / GBN, DIM / GBM, KSPLIT), 256>>>(
        xn, t1, upart, DIM, HID, NROI, DIM, HID, HID, NROI / KSPLIT,
        nullptr, nullptr, nullptr);
    reduceK_kernel<<<(utotal + 255) / 256, 256>>>(upart, u1, utotal, KSPLIT);

    // h1 = relu(xn @ u1 - d*t1 + bg1)
    gemm2_kernel<false, 1><<<dim3(HID / GBN, NROI / GBM, 1), 256>>>(
        xn, u1, h1, NROI, HID, DIM, DIM, HID, HID, DIM, bg1, dv, t1);

    // t2 = h1 @ Wg2         [4096,512] K=512
    gemm2_kernel<false, 0><<<dim3(HID / GBN, NROI / GBM, 1), 256>>>(
        h1, Wg2, t2, NROI, HID, HID, HID, HID, HID, HID, nullptr, nullptr, nullptr);

    // u2 = xn^T @ t2
    gemm2_kernel<true, 0><<<dim3(HID / GBN, DIM / GBM, KSPLIT), 256>>>(
        xn, t2, upart, DIM, HID, NROI, DIM, HID, HID, NROI / KSPLIT,
        nullptr, nullptr, nullptr);
    reduceK_kernel<<<(utotal + 255) / 256, 256>>>(upart, u2, utotal, KSPLIT);

    // h2 = relu(xn @ u2 - d*t2 + bg2)
    gemm2_kernel<false, 1><<<dim3(HID / GBN, NROI / GBM, 1), 256>>>(
        xn, u2, h2, NROI, HID, DIM, DIM, HID, HID, DIM, bg2, dv, t2);

    // bbox_pred = h2 @ W_bbox + b_bbox
    gemm_small_kernel<<<dim3((NBBX + BN - 1) / BN, NROI / BM, 1), 256>>>(
        h2, W_bbox, out + NROI + (size_t)NROI * NCLS,
        NROI, NBBX, HID, HID, NBBX, NBBX, b_bbox);

    // cls logits + softmax
    gemm_small_kernel<<<dim3(1, NROI / BM, 1), 256>>>(
        h2, W_cls, logits, NROI, NCLS, HID, HID, NCLS, NCLS, b_cls);
    softmax_kernel<<<NROI / 8, 256>>>(out);
}